// round 14
// baseline (speedup 1.0000x reference)
#include <cuda_runtime.h>
#include <cuda_bf16.h>
#include <cstdint>

#define BSZ 8192
#define DD  512
#define CC  512
#define MT  64                  // rows per CTA
#define NBLK (BSZ / MT)         // 128 CTAs
#define NSTG 8                  // K chunks of 64
#define TH  26.0f               // covers bf16-accumulate FMA-path error (5-sigma x2)
#define SLOTS 16
#define NTH 512
#define NMMA 384                // classes on tensor path; [384,512) on FMA path

// ---- device scratch ----
__device__ __nv_bfloat16 g_ch[CC * DD];
__device__ float g_cnorm[CC];
__device__ int   g_present[CC];      // zero-init; only 1s written (idempotent)
__device__ float g_rpart[2 * NBLK];
__device__ int   g_rcount;           // reset by last block each call

// ---- main smem layout (bytes) ----
#define SM_CN    0                   // 512 f
#define SM_TG    2048                // 64 i
#define SM_XN    2304                // 64 f
#define SM_RM    2560                // 64 f
#define SM_SCNT  2816                // 64 i
#define SM_CAND  3072                // 64*16 u16 = 2048
#define SM_RED   5120                // 64*10 f = 2560
#define SM_LP    7680                // 64*2 f = 512
#define SM_FIN   8192                // 16 f
#define SM_TILE  9216                // 1024-aligned
#define OFF_A    0                   // 64 rows x 128B
#define OFF_B    8192                // 512 rows x 128B
#define STG_S    73728               // one stage (A+B)
#define SMEM_BYTES (SM_TILE + 3 * STG_S)   // 230400 (triple buffer)

static __device__ __forceinline__ uint32_t s2u(const void* p) {
    uint32_t a;
    asm("{ .reg .u64 t; cvta.to.shared.u64 t, %1; cvt.u32.u64 %0, t; }" : "=r"(a) : "l"(p));
    return a;
}
static __device__ __forceinline__ void cp16(uint32_t dst, const void* src) {
    asm volatile("cp.async.cg.shared.global [%0], [%1], 16;" :: "r"(dst), "l"(src));
}
#define LDSM4(r0, r1, r2, r3, addr)                                             \
    asm volatile("ldmatrix.sync.aligned.m8n8.x4.shared.b16 {%0,%1,%2,%3}, [%4];" \
                 : "=r"(r0), "=r"(r1), "=r"(r2), "=r"(r3) : "r"(addr))
#define MMA(d, a, b0, b1)                                                        \
    asm volatile("mma.sync.aligned.m16n8k16.row.col.f32.bf16.bf16.f32 "          \
                 "{%0,%1,%2,%3},{%4,%5,%6,%7},{%8,%9},{%0,%1,%2,%3};"            \
                 : "+f"((d)[0]), "+f"((d)[1]), "+f"((d)[2]), "+f"((d)[3])        \
                 : "r"((a)[0]), "r"((a)[1]), "r"((a)[2]), "r"((a)[3]),           \
                   "r"(b0), "r"(b1))
#define LDS32(r, addr) \
    asm volatile("ld.shared.b32 %0, [%1];" : "=r"(r) : "r"(addr))
#define FMA2BF(acc_, a_, b_) \
    asm("fma.rn.bf16x2 %0, %1, %2, %0;" : "+r"(acc_) : "r"(a_), "r"(b_))

static __device__ __forceinline__ uint32_t packbf(float x, float y) {
    return ((uint32_t)__bfloat16_as_ushort(__float2bfloat16(y)) << 16)
         | __bfloat16_as_ushort(__float2bfloat16(x));
}
static __device__ __forceinline__ uint4 cvt8(float4 a, float4 b) {
    uint4 r;
    r.x = packbf(a.x, a.y); r.y = packbf(a.z, a.w);
    r.z = packbf(b.x, b.y); r.w = packbf(b.z, b.w);
    return r;
}
static __device__ __forceinline__ float sq4(float4 v, float s) {
    s = fmaf(v.x, v.x, s); s = fmaf(v.y, v.y, s);
    s = fmaf(v.z, v.z, s); s = fmaf(v.w, v.w, s);
    return s;
}
static __device__ __forceinline__ float bf2sum(uint32_t u) {
    __nv_bfloat162 bv = *reinterpret_cast<__nv_bfloat162*>(&u);
    float2 pf = __bfloat1622float2(bv);
    return pf.x + pf.y;
}
static __device__ __forceinline__ float dot512(const float4* xv, const float* crow, int lane) {
    const float4* c4 = (const float4*)crow;
    float s = 0.f;
#pragma unroll
    for (int i = 0; i < 4; i++) {
        float4 c = c4[lane + 32 * i];
        s = fmaf(xv[i].x, c.x, s); s = fmaf(xv[i].y, c.y, s);
        s = fmaf(xv[i].z, c.z, s); s = fmaf(xv[i].w, c.w, s);
    }
#pragma unroll
    for (int o = 16; o > 0; o >>= 1) s += __shfl_xor_sync(0xffffffffu, s, o);
    return s;
}

// ---------------------------------------------------------------------------
// prep (small): centers f32->bf16 + cnorm (blocks 0..63); presence marks (64..67)
// ---------------------------------------------------------------------------
__global__ void prep_kernel(const float* __restrict__ CT, const int* __restrict__ T) {
    if (blockIdx.x >= 64) {
        int base = (blockIdx.x - 64) * 2048 + threadIdx.x;
#pragma unroll
        for (int k = 0; k < 8; k++) g_present[T[base + 256 * k]] = 1;
        return;
    }
    int row  = blockIdx.x * 8 + (threadIdx.x >> 5);
    int lane = threadIdx.x & 31;
    const float* src = CT + (size_t)row * DD;
    float s = 0.f;
    const float4* p4 = (const float4*)src;
#pragma unroll
    for (int i = 0; i < 4; i++) {
        float4 v = p4[lane + 32 * i];
        s = sq4(v, s);
        uint2 hv;
        hv.x = packbf(v.x, v.y);
        hv.y = packbf(v.z, v.w);
        *(uint2*)(g_ch + (size_t)row * DD + (size_t)(lane + 32 * i) * 4) = hv;
    }
#pragma unroll
    for (int o = 16; o > 0; o >>= 1) s += __shfl_xor_sync(0xffffffffu, s, o);
    if (lane == 0) g_cnorm[row] = s;
}

// ---------------------------------------------------------------------------
// main: hybrid tensor+FMA. Warps 0-11 (3/SMSP): MMA over N[0,384), warp tile
// m32 x n64. Warps 12-15 (1/SMSP): bf16x2-FMA outer product over N[384,512)
// running in the MMA issue shadow. Triple-buffered, one barrier per stage.
// Accumulators union-aliased between roles (64 regs, no double allocation).
// ---------------------------------------------------------------------------
__global__ __launch_bounds__(NTH, 1) void main_kernel(
    const float* __restrict__ X, const float* __restrict__ CT,
    const int* __restrict__ T, float* out, int out_size)
{
    extern __shared__ char smem[];
    const uint32_t sb = s2u(smem);
    const int tid = threadIdx.x, lane = tid & 31, wid = tid >> 5;
    const float INF = __int_as_float(0x7f800000);

    float* cn     = (float*)(smem + SM_CN);
    int*   tg     = (int*)(smem + SM_TG);
    float* sxn    = (float*)(smem + SM_XN);
    float* rowmin = (float*)(smem + SM_RM);
    int*   scnt   = (int*)(smem + SM_SCNT);
    unsigned short* scand = (unsigned short*)(smem + SM_CAND);
    float* red    = (float*)(smem + SM_RED);
    float* lp     = (float*)(smem + SM_LP);
    float* fin    = (float*)(smem + SM_FIN);

    if (tid < CC) cn[tid] = g_present[tid] ? g_cnorm[tid] : INF;
    if (tid < MT) { tg[tid] = T[blockIdx.x * MT + tid]; scnt[tid] = 0; }

    // role constants
    const int wr = (wid < 12) ? (wid / 6) : 0;       // MMA: 2 x 6 grid
    const int wc = (wid < 12) ? (wid % 6) : 0;
    const int fw = wid - 12;                          // FMA warp id 0..3
    const int rg = lane >> 2, cg = lane & 3;          // FMA lane grid 8x4

    // ---- A producer: 64 rows x 8 threads; each converts 2 float4 -> uint4 ----
    const int arow = tid >> 3, aq = tid & 7;
    const float4* Ag = (const float4*)(X + (size_t)(blockIdx.x * MT + arow) * DD);
    const uint32_t aoff0 = (uint32_t)(arow * 128 + aq * 16);
    const uint32_t aoff_sw = aoff0 ^ ((aoff0 >> 3) & 0x70);
    float sq = 0.f;

    // ---- B producer: 512 rows x 8 chunks = 4096 cp16 / 512 threads = 8 each ----
    const int brow0 = tid >> 3, bq = tid & 7;
#define BFILL(ST, BUF)                                                            \
    do {                                                                          \
        const int st_ = (ST);                                                     \
        const uint32_t dstb_ = sb + SM_TILE + (uint32_t)(BUF) * STG_S + OFF_B;    \
        _Pragma("unroll")                                                         \
        for (int i_ = 0; i_ < 8; i_++) {                                          \
            int row_ = brow0 + 64 * i_;                                           \
            uint32_t off_ = (uint32_t)(row_ * 128 + bq * 16);                     \
            off_ ^= ((off_ >> 3) & 0x70);                                         \
            cp16(dstb_ + off_, g_ch + (size_t)row_ * DD + st_ * 64 + bq * 8);     \
        }                                                                         \
        asm volatile("cp.async.commit_group;");                                   \
    } while (0)

    // ---- prologue: stages 0,1 into buffers 0,1 ----
#pragma unroll
    for (int st = 0; st < 2; st++) {
        float4 u0 = Ag[st * 16 + aq * 2], u1 = Ag[st * 16 + aq * 2 + 1];
        sq = sq4(u0, sq); sq = sq4(u1, sq);
        *(uint4*)(smem + SM_TILE + st * STG_S + OFF_A + aoff_sw) = cvt8(u0, u1);
    }
    BFILL(0, 0);
    BFILL(1, 1);
    float4 ar0 = Ag[2 * 16 + aq * 2], ar1 = Ag[2 * 16 + aq * 2 + 1];

    // accumulators: union-aliased between roles (warp-uniform branch)
    union AccU {
        float    f[2][8][4];    // MMA: [m-half][n-tile][elem]
        uint32_t u[8][8];       // FMA: [row-i][class-j] bf16x2 (k-parity pair)
    } acc;
#pragma unroll
    for (int i = 0; i < 8; i++)
#pragma unroll
        for (int j = 0; j < 8; j++) acc.u[i][j] = 0u;

    const int rA       = wr * 32 + (lane & 15);
    const uint32_t swz = (uint32_t)(lane & 7) << 4;
    const uint32_t kA  = (uint32_t)(lane >> 4) << 4;
    const uint32_t kB  = (uint32_t)((lane >> 3) & 1) << 4;
    const int nB       = ((lane >> 4) << 3) + (lane & 7);
    // FMA addressing constants
    const uint32_t fB0 = (uint32_t)((NMMA + fw * 32 + cg * 8) * 128);
    const uint32_t fswzA = (uint32_t)rg << 4;

    int bcur = 0;                       // kt % 3
    for (int kt = 0; kt < NSTG; kt++) {
        if (kt == NSTG - 1) asm volatile("cp.async.wait_group 0;");
        else                asm volatile("cp.async.wait_group 1;");
        __syncthreads();                // the ONLY barrier per stage

        const uint32_t tb = sb + SM_TILE + (uint32_t)bcur * STG_S;

        if (wid < 12) {
            // ---- tensor role: N [0,384) ----
            const uint32_t aA0   = tb + OFF_A + (uint32_t)rA * 128;
            const uint32_t bbase = tb + OFF_B + (uint32_t)((wc * 64 + nB) * 128);
#pragma unroll
            for (int kk = 0; kk < 4; kk++) {
                const uint32_t ka = ((uint32_t)(kk * 32) + kA) ^ swz;
                const uint32_t kb = ((uint32_t)(kk * 32) + kB) ^ swz;
                uint32_t ah[2][4];
                LDSM4(ah[0][0], ah[0][1], ah[0][2], ah[0][3], aA0 + ka);
                LDSM4(ah[1][0], ah[1][1], ah[1][2], ah[1][3], aA0 + 16 * 128 + ka);
#pragma unroll
                for (int nb = 0; nb < 4; nb++) {
                    uint32_t b[4];
                    LDSM4(b[0], b[1], b[2], b[3], bbase + (uint32_t)(nb * 2048) + kb);
                    MMA(acc.f[0][nb * 2 + 0], ah[0], b[0], b[1]);
                    MMA(acc.f[0][nb * 2 + 1], ah[0], b[2], b[3]);
                    MMA(acc.f[1][nb * 2 + 0], ah[1], b[0], b[1]);
                    MMA(acc.f[1][nb * 2 + 1], ah[1], b[2], b[3]);
                }
            }
        } else {
            // ---- FMA role: N [384,512), bf16x2 outer product ----
            const uint32_t tbA = tb + OFF_A;
            const uint32_t tbB = tb + OFF_B + fB0;
#pragma unroll 4
            for (int kp = 0; kp < 32; kp++) {
                const uint32_t kp4 = (uint32_t)(kp * 4);
                const uint32_t ka = kp4 ^ fswzA;
                uint32_t areg[8], breg[8];
#pragma unroll
                for (int i = 0; i < 8; i++)
                    LDS32(areg[i], tbA + (uint32_t)((rg + 8 * i) * 128) + ka);
#pragma unroll
                for (int j = 0; j < 8; j++)
                    LDS32(breg[j], tbB + (uint32_t)(j * 128) + (kp4 ^ ((uint32_t)j << 4)));
#pragma unroll
                for (int i = 0; i < 8; i++)
#pragma unroll
                    for (int j = 0; j < 8; j++)
                        FMA2BF(acc.u[i][j], areg[i], breg[j]);
            }
        }
        // fill stage kt+2 into buffer (kt+2)%3 — no barrier needed (triple buf)
        if (kt + 2 < NSTG) {
            const int bfill = (bcur + 2 >= 3) ? bcur - 1 : bcur + 2;
            sq = sq4(ar0, sq); sq = sq4(ar1, sq);
            *(uint4*)(smem + SM_TILE + (size_t)bfill * STG_S + OFF_A + aoff_sw)
                = cvt8(ar0, ar1);
            BFILL(kt + 2, bfill);
            if (kt + 3 < NSTG) {
                ar0 = Ag[(kt + 3) * 16 + aq * 2];
                ar1 = Ag[(kt + 3) * 16 + aq * 2 + 1];
            }
        }
        bcur = (bcur + 1 >= 3) ? 0 : bcur + 1;
    }
#undef BFILL

    // ---- row norms: reduce over the 8 q-threads of each row ----
    sq += __shfl_xor_sync(0xffffffffu, sq, 1);
    sq += __shfl_xor_sync(0xffffffffu, sq, 2);
    sq += __shfl_xor_sync(0xffffffffu, sq, 4);
    if (aq == 0) sxn[arow] = sq;

    // ---- pass 1: approx row-min over non-own classes (role-split) ----
    if (wid < 12) {
        float rmin[2][2];
#pragma unroll
        for (int mb = 0; mb < 2; mb++) { rmin[mb][0] = INF; rmin[mb][1] = INF; }
#pragma unroll
        for (int mb = 0; mb < 2; mb++)
#pragma unroll
            for (int j = 0; j < 8; j++) {
                const int colb = wc * 64 + j * 8 + (lane & 3) * 2;
#pragma unroll
                for (int e = 0; e < 4; e++) {
                    const int cl = colb + (e & 1);
                    const int lr = wr * 32 + mb * 16 + ((e >> 1) << 3) + (lane >> 2);
                    const float v = fmaf(-2.f, acc.f[mb][j][e], cn[cl]);
                    if (cl != tg[lr]) rmin[mb][e >> 1] = fminf(rmin[mb][e >> 1], v);
                }
            }
#pragma unroll
        for (int mb = 0; mb < 2; mb++)
#pragma unroll
            for (int rr = 0; rr < 2; rr++) {
                float m = rmin[mb][rr];
                m = fminf(m, __shfl_xor_sync(0xffffffffu, m, 1));
                m = fminf(m, __shfl_xor_sync(0xffffffffu, m, 2));
                if ((lane & 3) == 0)
                    red[(wr * 32 + mb * 16 + rr * 8 + (lane >> 2)) * 10 + wc] = m;
            }
    } else {
        const int cls0 = NMMA + fw * 32 + cg * 8;
#pragma unroll
        for (int i = 0; i < 8; i++) {
            const int row = rg + 8 * i;
            const int own = tg[row];
            float m = INF;
#pragma unroll
            for (int j = 0; j < 8; j++) {
                const float v = fmaf(-2.f, bf2sum(acc.u[i][j]), cn[cls0 + j]);
                if (cls0 + j != own) m = fminf(m, v);
            }
            m = fminf(m, __shfl_xor_sync(0xffffffffu, m, 1));
            m = fminf(m, __shfl_xor_sync(0xffffffffu, m, 2));
            if (cg == 0) red[row * 10 + 6 + fw] = m;
        }
    }
    __syncthreads();
    if (tid < MT) {
        float m = INF;
#pragma unroll
        for (int i = 0; i < 10; i++) m = fminf(m, red[tid * 10 + i]);
        rowmin[tid] = m;
    }
    __syncthreads();

    // ---- pass 2: mark candidates (role-split) ----
    if (wid < 12) {
#pragma unroll
        for (int mb = 0; mb < 2; mb++)
#pragma unroll
            for (int j = 0; j < 8; j++) {
                const int colb = wc * 64 + j * 8 + (lane & 3) * 2;
#pragma unroll
                for (int e = 0; e < 4; e++) {
                    const int cl = colb + (e & 1);
                    const int lr = wr * 32 + mb * 16 + ((e >> 1) << 3) + (lane >> 2);
                    const float v = fmaf(-2.f, acc.f[mb][j][e], cn[cl]);
                    if (cl != tg[lr] && v < 1.0e30f && v <= rowmin[lr] + TH) {
                        int s = atomicAdd(&scnt[lr], 1);
                        if (s < SLOTS) scand[lr * SLOTS + s] = (unsigned short)cl;
                    }
                }
            }
    } else {
        const int cls0 = NMMA + fw * 32 + cg * 8;
#pragma unroll
        for (int i = 0; i < 8; i++) {
            const int row = rg + 8 * i;
            const int own = tg[row];
            const float rm = rowmin[row] + TH;
#pragma unroll
            for (int j = 0; j < 8; j++) {
                const float v = fmaf(-2.f, bf2sum(acc.u[i][j]), cn[cls0 + j]);
                if (cls0 + j != own && v < 1.0e30f && v <= rm) {
                    int s = atomicAdd(&scnt[row], 1);
                    if (s < SLOTS) scand[row * SLOTS + s] = (unsigned short)(cls0 + j);
                }
            }
        }
    }
    __syncthreads();

    // ---- refine: exact fp32 dots; warp w handles rows w*4..w*4+3 ----
#pragma unroll 1
    for (int rr = 0; rr < 4; rr++) {
        const int lr = wid * 4 + rr;
        const int grow = blockIdx.x * MT + lr;
        const float4* xr = (const float4*)(X + (size_t)grow * DD);
        float4 xv[4];
#pragma unroll
        for (int i = 0; i < 4; i++) xv[i] = xr[lane + 32 * i];
        const int own = tg[lr];
        const float dot_own = dot512(xv, CT + (size_t)own * DD, lane);
        int cnt = scnt[lr]; if (cnt > SLOTS) cnt = SLOTS;
        float vmin = INF;
        for (int i = 0; i < cnt; i++) {
            int c = scand[lr * SLOTS + i];
            float d = dot512(xv, CT + (size_t)c * DD, lane);
            vmin = fminf(vmin, cn[c] - 2.f * d);
        }
        const float xn = sxn[lr];
        float dap = sqrtf(fmaxf(xn + cn[own] - 2.f * dot_own, 1e-12f));
        float dan = sqrtf(fmaxf(xn + vmin, 1e-12f));
        if (lane == 0) {
            lp[2 * lr]     = fmaxf(0.f, dap - dan + 1.f);
            lp[2 * lr + 1] = (dan > dap) ? 1.f : 0.f;
        }
    }
    __syncthreads();

    // ---- per-CTA reduction + global last-block finish ----
    __shared__ int slast;
    if (tid < MT) {
        float li = lp[2 * tid], pi = lp[2 * tid + 1];
#pragma unroll
        for (int o = 16; o > 0; o >>= 1) {
            li += __shfl_xor_sync(0xffffffffu, li, o);
            pi += __shfl_xor_sync(0xffffffffu, pi, o);
        }
        if ((tid & 31) == 0) { fin[tid >> 5] = li; fin[4 + (tid >> 5)] = pi; }
    }
    __syncthreads();
    if (tid == 0) {
        g_rpart[2 * blockIdx.x]     = fin[0] + fin[1];
        g_rpart[2 * blockIdx.x + 1] = fin[4] + fin[5];
        __threadfence();
        slast = (atomicAdd(&g_rcount, 1) == NBLK - 1);
    }
    __syncthreads();
    if (slast) {
        float a = 0.f, b = 0.f;
        if (tid < NBLK) { a = g_rpart[2 * tid]; b = g_rpart[2 * tid + 1]; }
#pragma unroll
        for (int o = 16; o > 0; o >>= 1) {
            a += __shfl_xor_sync(0xffffffffu, a, o);
            b += __shfl_xor_sync(0xffffffffu, b, o);
        }
        if (tid < NBLK && (tid & 31) == 0) { fin[tid >> 5] = a; fin[4 + (tid >> 5)] = b; }
        __syncthreads();
        if (tid == 0) {
            float sa = fin[0] + fin[1] + fin[2] + fin[3];
            float sb = fin[4] + fin[5] + fin[6] + fin[7];
            out[0] = sa / (float)BSZ;
            if (out_size > 1) out[1] = sb / (float)BSZ;
            g_rcount = 0;            // reset for next graph replay
        }
    }
}

// ---------------------------------------------------------------------------
extern "C" void kernel_launch(void* const* d_in, const int* in_sizes, int n_in,
                              void* d_out, int out_size) {
    const float* X  = nullptr;
    const float* CT = nullptr;
    const int*   T  = nullptr;
    for (int i = 0; i < n_in; i++) {
        if (in_sizes[i] == BSZ * DD)     X  = (const float*)d_in[i];
        else if (in_sizes[i] == CC * DD) CT = (const float*)d_in[i];
        else if (in_sizes[i] == BSZ)     T  = (const int*)d_in[i];
    }
    cudaFuncSetAttribute(main_kernel,
                         cudaFuncAttributeMaxDynamicSharedMemorySize, SMEM_BYTES);

    prep_kernel<<<68, 256>>>(CT, T);
    main_kernel<<<NBLK, NTH, SMEM_BYTES>>>(X, CT, T, (float*)d_out, out_size);
}

// round 15
// speedup vs baseline: 1.8706x; 1.8706x over previous
#include <cuda_runtime.h>
#include <cuda_bf16.h>
#include <cstdint>

#define BSZ 8192
#define DD  512
#define CC  512
#define MT  64                  // rows per CTA
#define NBLK (BSZ / MT)         // 128 CTAs
#define NSTG 8                  // K chunks of 64
#define TH  3.0f
#define SLOTS 16
#define NTH 512

// ---- device scratch ----
__device__ __nv_bfloat16 g_ch[CC * DD];
__device__ float g_cnorm[CC];
__device__ int   g_present[CC];      // zero-init; only 1s written (idempotent)
__device__ float g_rpart[2 * NBLK];
__device__ int   g_rcount;           // reset by last block each call

// ---- main smem layout (bytes) ----
#define SM_CN    0                   // 512 f
#define SM_TG    2048                // 64 i
#define SM_XN    2304                // 64 f
#define SM_RM    2560                // 64 f
#define SM_SCNT  2816                // 64 i
#define SM_CAND  3072                // 64*16 u16
#define SM_RED   5120                // 64*8 f
#define SM_LP    7168                // 64*2 f
#define SM_FIN   7680                // 8 f
#define SM_TILE  8192                // 1024-aligned
#define OFF_A    0                   // 64 rows x 128B
#define OFF_B    8192                // 512 rows x 128B
#define STG_S    73728               // one stage (A+B)
#define SMEM_BYTES (SM_TILE + 3 * STG_S)   // 229376 (triple buffer)

static __device__ __forceinline__ uint32_t s2u(const void* p) {
    uint32_t a;
    asm("{ .reg .u64 t; cvta.to.shared.u64 t, %1; cvt.u32.u64 %0, t; }" : "=r"(a) : "l"(p));
    return a;
}
static __device__ __forceinline__ void cp16(uint32_t dst, const void* src) {
    asm volatile("cp.async.cg.shared.global [%0], [%1], 16;" :: "r"(dst), "l"(src));
}
#define LDSM4(r0, r1, r2, r3, addr)                                             \
    asm volatile("ldmatrix.sync.aligned.m8n8.x4.shared.b16 {%0,%1,%2,%3}, [%4];" \
                 : "=r"(r0), "=r"(r1), "=r"(r2), "=r"(r3) : "r"(addr))
#define MMA(d, a, b0, b1)                                                        \
    asm volatile("mma.sync.aligned.m16n8k16.row.col.f32.bf16.bf16.f32 "          \
                 "{%0,%1,%2,%3},{%4,%5,%6,%7},{%8,%9},{%0,%1,%2,%3};"            \
                 : "+f"((d)[0]), "+f"((d)[1]), "+f"((d)[2]), "+f"((d)[3])        \
                 : "r"((a)[0]), "r"((a)[1]), "r"((a)[2]), "r"((a)[3]),           \
                   "r"(b0), "r"(b1))

static __device__ __forceinline__ uint32_t packbf(float x, float y) {
    return ((uint32_t)__bfloat16_as_ushort(__float2bfloat16(y)) << 16)
         | __bfloat16_as_ushort(__float2bfloat16(x));
}
static __device__ __forceinline__ uint4 cvt8(float4 a, float4 b) {
    uint4 r;
    r.x = packbf(a.x, a.y); r.y = packbf(a.z, a.w);
    r.z = packbf(b.x, b.y); r.w = packbf(b.z, b.w);
    return r;
}
static __device__ __forceinline__ float sq4(float4 v, float s) {
    s = fmaf(v.x, v.x, s); s = fmaf(v.y, v.y, s);
    s = fmaf(v.z, v.z, s); s = fmaf(v.w, v.w, s);
    return s;
}
static __device__ __forceinline__ float dot512(const float4* xv, const float* crow, int lane) {
    const float4* c4 = (const float4*)crow;
    float s = 0.f;
#pragma unroll
    for (int i = 0; i < 4; i++) {
        float4 c = c4[lane + 32 * i];
        s = fmaf(xv[i].x, c.x, s); s = fmaf(xv[i].y, c.y, s);
        s = fmaf(xv[i].z, c.z, s); s = fmaf(xv[i].w, c.w, s);
    }
#pragma unroll
    for (int o = 16; o > 0; o >>= 1) s += __shfl_xor_sync(0xffffffffu, s, o);
    return s;
}

// ---------------------------------------------------------------------------
// prep (small): centers f32->bf16 + cnorm (blocks 0..63); presence marks (64..67)
// ---------------------------------------------------------------------------
__global__ void prep_kernel(const float* __restrict__ CT, const int* __restrict__ T) {
    if (blockIdx.x >= 64) {
        int base = (blockIdx.x - 64) * 2048 + threadIdx.x;
#pragma unroll
        for (int k = 0; k < 8; k++) g_present[T[base + 256 * k]] = 1;
        return;
    }
    int row  = blockIdx.x * 8 + (threadIdx.x >> 5);
    int lane = threadIdx.x & 31;
    const float* src = CT + (size_t)row * DD;
    float s = 0.f;
    const float4* p4 = (const float4*)src;
#pragma unroll
    for (int i = 0; i < 4; i++) {
        float4 v = p4[lane + 32 * i];
        s = sq4(v, s);
        uint2 hv;
        hv.x = packbf(v.x, v.y);
        hv.y = packbf(v.z, v.w);
        *(uint2*)(g_ch + (size_t)row * DD + (size_t)(lane + 32 * i) * 4) = hv;
    }
#pragma unroll
    for (int o = 16; o > 0; o >>= 1) s += __shfl_xor_sync(0xffffffffu, s, o);
    if (lane == 0) g_cnorm[row] = s;
}

// ---------------------------------------------------------------------------
// main: M64 x N512 bf16 HMMA, 512 threads, 16 warps (2 wr x 8 wc), warp tile
// m32 x n64. Triple-buffered, one barrier per stage. Launched with PDL:
// the A-prologue (independent of prep) runs before griddepcontrol.wait;
// everything touching g_ch/g_cnorm/g_present runs after.
// ---------------------------------------------------------------------------
__global__ __launch_bounds__(NTH, 1) void main_kernel(
    const float* __restrict__ X, const float* __restrict__ CT,
    const int* __restrict__ T, float* out, int out_size)
{
    extern __shared__ char smem[];
    const uint32_t sb = s2u(smem);
    const int tid = threadIdx.x, lane = tid & 31, wid = tid >> 5;
    const int wr = wid >> 3, wc = wid & 7;
    const float INF = __int_as_float(0x7f800000);

    float* cn     = (float*)(smem + SM_CN);
    int*   tg     = (int*)(smem + SM_TG);
    float* sxn    = (float*)(smem + SM_XN);
    float* rowmin = (float*)(smem + SM_RM);
    int*   scnt   = (int*)(smem + SM_SCNT);
    unsigned short* scand = (unsigned short*)(smem + SM_CAND);
    float* red    = (float*)(smem + SM_RED);
    float* lp     = (float*)(smem + SM_LP);
    float* fin    = (float*)(smem + SM_FIN);

    // ---- prep-independent prologue (overlaps prep via PDL) ----
    if (tid < MT) { tg[tid] = T[blockIdx.x * MT + tid]; scnt[tid] = 0; }

    // A producer: 64 rows x 8 threads; each converts 2 float4 -> uint4
    const int arow = tid >> 3, aq = tid & 7;
    const float4* Ag = (const float4*)(X + (size_t)(blockIdx.x * MT + arow) * DD);
    const uint32_t aoff0 = (uint32_t)(arow * 128 + aq * 16);
    const uint32_t aoff_sw = aoff0 ^ ((aoff0 >> 3) & 0x70);
    float sq = 0.f;

#pragma unroll
    for (int st = 0; st < 2; st++) {
        float4 u0 = Ag[st * 16 + aq * 2], u1 = Ag[st * 16 + aq * 2 + 1];
        sq = sq4(u0, sq); sq = sq4(u1, sq);
        *(uint4*)(smem + SM_TILE + st * STG_S + OFF_A + aoff_sw) = cvt8(u0, u1);
    }
    float4 ar0 = Ag[2 * 16 + aq * 2], ar1 = Ag[2 * 16 + aq * 2 + 1];

    // ---- wait for prep outputs (g_ch, g_cnorm, g_present) ----
    asm volatile("griddepcontrol.wait;" ::: "memory");

    if (tid < CC) cn[tid] = g_present[tid] ? g_cnorm[tid] : INF;

    // B producer: 512 rows x 8 chunks = 4096 cp16 / 512 threads = 8 each
    const int brow0 = tid >> 3, bq = tid & 7;
#define BFILL(ST, BUF)                                                            \
    do {                                                                          \
        const int st_ = (ST);                                                     \
        const uint32_t dstb_ = sb + SM_TILE + (uint32_t)(BUF) * STG_S + OFF_B;    \
        _Pragma("unroll")                                                         \
        for (int i_ = 0; i_ < 8; i_++) {                                          \
            int row_ = brow0 + 64 * i_;                                           \
            uint32_t off_ = (uint32_t)(row_ * 128 + bq * 16);                     \
            off_ ^= ((off_ >> 3) & 0x70);                                         \
            cp16(dstb_ + off_, g_ch + (size_t)row_ * DD + st_ * 64 + bq * 8);     \
        }                                                                         \
        asm volatile("cp.async.commit_group;");                                   \
    } while (0)

    BFILL(0, 0);
    BFILL(1, 1);

    float acc[2][8][4];
#pragma unroll
    for (int mb = 0; mb < 2; mb++)
#pragma unroll
        for (int j = 0; j < 8; j++)
#pragma unroll
            for (int e = 0; e < 4; e++) acc[mb][j][e] = 0.f;

    const int rA       = wr * 32 + (lane & 15);
    const uint32_t swz = (uint32_t)(lane & 7) << 4;
    const uint32_t kA  = (uint32_t)(lane >> 4) << 4;
    const uint32_t kB  = (uint32_t)((lane >> 3) & 1) << 4;
    const int nB       = ((lane >> 4) << 3) + (lane & 7);

    int bcur = 0;                       // kt % 3
    for (int kt = 0; kt < NSTG; kt++) {
        if (kt == NSTG - 1) asm volatile("cp.async.wait_group 0;");
        else                asm volatile("cp.async.wait_group 1;");
        __syncthreads();                // the ONLY barrier per stage

        const uint32_t tb    = sb + SM_TILE + (uint32_t)bcur * STG_S;
        const uint32_t aA0   = tb + OFF_A + (uint32_t)rA * 128;
        const uint32_t bbase = tb + OFF_B + (uint32_t)((wc * 64 + nB) * 128);

#pragma unroll
        for (int kk = 0; kk < 4; kk++) {
            const uint32_t ka = ((uint32_t)(kk * 32) + kA) ^ swz;
            const uint32_t kb = ((uint32_t)(kk * 32) + kB) ^ swz;
            uint32_t ah[2][4];
            LDSM4(ah[0][0], ah[0][1], ah[0][2], ah[0][3], aA0 + ka);
            LDSM4(ah[1][0], ah[1][1], ah[1][2], ah[1][3], aA0 + 16 * 128 + ka);
#pragma unroll
            for (int nb = 0; nb < 4; nb++) {
                uint32_t b[4];
                LDSM4(b[0], b[1], b[2], b[3], bbase + (uint32_t)(nb * 2048) + kb);
                MMA(acc[0][nb * 2 + 0], ah[0], b[0], b[1]);
                MMA(acc[0][nb * 2 + 1], ah[0], b[2], b[3]);
                MMA(acc[1][nb * 2 + 0], ah[1], b[0], b[1]);
                MMA(acc[1][nb * 2 + 1], ah[1], b[2], b[3]);
            }
        }
        // fill stage kt+2 into buffer (kt+2)%3 — no barrier needed (triple buf)
        if (kt + 2 < NSTG) {
            const int bfill = (bcur + 2 >= 3) ? bcur - 1 : bcur + 2;
            sq = sq4(ar0, sq); sq = sq4(ar1, sq);
            *(uint4*)(smem + SM_TILE + (size_t)bfill * STG_S + OFF_A + aoff_sw)
                = cvt8(ar0, ar1);
            BFILL(kt + 2, bfill);
            if (kt + 3 < NSTG) {
                ar0 = Ag[(kt + 3) * 16 + aq * 2];
                ar1 = Ag[(kt + 3) * 16 + aq * 2 + 1];
            }
        }
        bcur = (bcur + 1 >= 3) ? 0 : bcur + 1;
    }
#undef BFILL

    // ---- row norms: reduce over the 8 q-threads of each row ----
    sq += __shfl_xor_sync(0xffffffffu, sq, 1);
    sq += __shfl_xor_sync(0xffffffffu, sq, 2);
    sq += __shfl_xor_sync(0xffffffffu, sq, 4);
    if (aq == 0) sxn[arow] = sq;

    // ---- pass 1: approx row-min over non-own classes ----
    float rmin[2][2];
#pragma unroll
    for (int mb = 0; mb < 2; mb++) { rmin[mb][0] = INF; rmin[mb][1] = INF; }
#pragma unroll
    for (int mb = 0; mb < 2; mb++)
#pragma unroll
        for (int j = 0; j < 8; j++) {
            const int colb = wc * 64 + j * 8 + (lane & 3) * 2;
#pragma unroll
            for (int e = 0; e < 4; e++) {
                const int cl = colb + (e & 1);
                const int lr = wr * 32 + mb * 16 + ((e >> 1) << 3) + (lane >> 2);
                const float v = fmaf(-2.f, acc[mb][j][e], cn[cl]);
                if (cl != tg[lr]) rmin[mb][e >> 1] = fminf(rmin[mb][e >> 1], v);
            }
        }
#pragma unroll
    for (int mb = 0; mb < 2; mb++)
#pragma unroll
        for (int rr = 0; rr < 2; rr++) {
            float m = rmin[mb][rr];
            m = fminf(m, __shfl_xor_sync(0xffffffffu, m, 1));
            m = fminf(m, __shfl_xor_sync(0xffffffffu, m, 2));
            if ((lane & 3) == 0)
                red[(wr * 32 + mb * 16 + rr * 8 + (lane >> 2)) * 8 + wc] = m;
        }
    __syncthreads();
    if (tid < MT) {
        float m = INF;
#pragma unroll
        for (int i = 0; i < 8; i++) m = fminf(m, red[tid * 8 + i]);
        rowmin[tid] = m;
    }
    __syncthreads();

    // ---- pass 2: mark candidates ----
#pragma unroll
    for (int mb = 0; mb < 2; mb++)
#pragma unroll
        for (int j = 0; j < 8; j++) {
            const int colb = wc * 64 + j * 8 + (lane & 3) * 2;
#pragma unroll
            for (int e = 0; e < 4; e++) {
                const int cl = colb + (e & 1);
                const int lr = wr * 32 + mb * 16 + ((e >> 1) << 3) + (lane >> 2);
                const float v = fmaf(-2.f, acc[mb][j][e], cn[cl]);
                if (cl != tg[lr] && v < 1.0e30f && v <= rowmin[lr] + TH) {
                    int s = atomicAdd(&scnt[lr], 1);
                    if (s < SLOTS) scand[lr * SLOTS + s] = (unsigned short)cl;
                }
            }
        }
    __syncthreads();

    // ---- refine: exact fp32 dots; warp w handles rows w*4..w*4+3 ----
#pragma unroll 1
    for (int rr = 0; rr < 4; rr++) {
        const int lr = wid * 4 + rr;
        const int grow = blockIdx.x * MT + lr;
        const float4* xr = (const float4*)(X + (size_t)grow * DD);
        float4 xv[4];
#pragma unroll
        for (int i = 0; i < 4; i++) xv[i] = xr[lane + 32 * i];
        const int own = tg[lr];
        const float dot_own = dot512(xv, CT + (size_t)own * DD, lane);
        int cnt = scnt[lr]; if (cnt > SLOTS) cnt = SLOTS;
        float vmin = INF;
        for (int i = 0; i < cnt; i++) {
            int c = scand[lr * SLOTS + i];
            float d = dot512(xv, CT + (size_t)c * DD, lane);
            vmin = fminf(vmin, cn[c] - 2.f * d);
        }
        const float xn = sxn[lr];
        float dap = sqrtf(fmaxf(xn + cn[own] - 2.f * dot_own, 1e-12f));
        float dan = sqrtf(fmaxf(xn + vmin, 1e-12f));
        if (lane == 0) {
            lp[2 * lr]     = fmaxf(0.f, dap - dan + 1.f);
            lp[2 * lr + 1] = (dan > dap) ? 1.f : 0.f;
        }
    }
    __syncthreads();

    // ---- per-CTA reduction + global last-block finish ----
    __shared__ int slast;
    if (tid < MT) {
        float li = lp[2 * tid], pi = lp[2 * tid + 1];
#pragma unroll
        for (int o = 16; o > 0; o >>= 1) {
            li += __shfl_xor_sync(0xffffffffu, li, o);
            pi += __shfl_xor_sync(0xffffffffu, pi, o);
        }
        if ((tid & 31) == 0) { fin[tid >> 5] = li; fin[4 + (tid >> 5)] = pi; }
    }
    __syncthreads();
    if (tid == 0) {
        g_rpart[2 * blockIdx.x]     = fin[0] + fin[1];
        g_rpart[2 * blockIdx.x + 1] = fin[4] + fin[5];
        __threadfence();
        slast = (atomicAdd(&g_rcount, 1) == NBLK - 1);
    }
    __syncthreads();
    if (slast) {
        float a = 0.f, b = 0.f;
        if (tid < NBLK) { a = g_rpart[2 * tid]; b = g_rpart[2 * tid + 1]; }
#pragma unroll
        for (int o = 16; o > 0; o >>= 1) {
            a += __shfl_xor_sync(0xffffffffu, a, o);
            b += __shfl_xor_sync(0xffffffffu, b, o);
        }
        if (tid < NBLK && (tid & 31) == 0) { fin[tid >> 5] = a; fin[4 + (tid >> 5)] = b; }
        __syncthreads();
        if (tid == 0) {
            float sa = fin[0] + fin[1] + fin[2] + fin[3];
            float sb = fin[4] + fin[5] + fin[6] + fin[7];
            out[0] = sa / (float)BSZ;
            if (out_size > 1) out[1] = sb / (float)BSZ;
            g_rcount = 0;            // reset for next graph replay
        }
    }
}

// ---------------------------------------------------------------------------
extern "C" void kernel_launch(void* const* d_in, const int* in_sizes, int n_in,
                              void* d_out, int out_size) {
    const float* X  = nullptr;
    const float* CT = nullptr;
    const int*   T  = nullptr;
    for (int i = 0; i < n_in; i++) {
        if (in_sizes[i] == BSZ * DD)     X  = (const float*)d_in[i];
        else if (in_sizes[i] == CC * DD) CT = (const float*)d_in[i];
        else if (in_sizes[i] == BSZ)     T  = (const int*)d_in[i];
    }
    cudaFuncSetAttribute(main_kernel,
                         cudaFuncAttributeMaxDynamicSharedMemorySize, SMEM_BYTES);

    prep_kernel<<<68, 256>>>(CT, T);

    // PDL launch: main starts while prep runs; it blocks at griddepcontrol.wait
    // until prep completes, having already executed its prep-independent prologue.
    cudaLaunchConfig_t cfg = {};
    cfg.gridDim = dim3(NBLK);
    cfg.blockDim = dim3(NTH);
    cfg.dynamicSmemBytes = SMEM_BYTES;
    cfg.stream = 0;
    cudaLaunchAttribute attrs[1];
    attrs[0].id = cudaLaunchAttributeProgrammaticStreamSerialization;
    attrs[0].val.programmaticStreamSerializationAllowed = 1;
    cfg.attrs = attrs;
    cfg.numAttrs = 1;
    cudaLaunchKernelEx(&cfg, main_kernel, X, CT, T, (float*)d_out, out_size);
}